// round 8
// baseline (speedup 1.0000x reference)
#include <cuda_runtime.h>
#include <cuda_bf16.h>
#include <math.h>
#include <stdint.h>

#define ROWS   4096
#define DMODEL 1024
#define TSEQ   2048
#define DK     64
#define NGRP   32
#define OUT_ELEMS 4194304
#define ATTN_PER_G 4194304
#define GRP_STRIDE 131072

// Scratch
__device__ float g_q[ROWS * DMODEL];
__device__ float g_k[ROWS * DMODEL];
__device__ float g_v[ROWS * DMODEL];
__device__ __nv_bfloat16 g_xh[ROWS * DMODEL], g_xl[ROWS * DMODEL];
__device__ __nv_bfloat16 g_qh[ROWS * DMODEL], g_ql[ROWS * DMODEL];
__device__ __nv_bfloat16 g_kh[ROWS * DMODEL], g_kl[ROWS * DMODEL];
__device__ __nv_bfloat16 g_wh[3 * DMODEL * DMODEL], g_wl[3 * DMODEL * DMODEL];
__device__ __nv_bfloat16 g_vh[NGRP * DK * TSEQ], g_vl[NGRP * DK * TSEQ];
__device__ __nv_bfloat16 g_ph[134217728];   // P hi  [g][2048][2048]
__device__ __nv_bfloat16 g_pl[134217728];   // P lo

// ===========================================================================
__device__ __forceinline__ uint32_t smem_u32(const void* p) {
    uint32_t a;
    asm("{ .reg .u64 t; cvta.to.shared.u64 t, %1; cvt.u32.u64 %0, t; }"
        : "=r"(a) : "l"(p));
    return a;
}

__device__ __forceinline__ void ldsm4(uint32_t* r, uint32_t addr) {
    asm volatile("ldmatrix.sync.aligned.m8n8.x4.shared.b16 {%0,%1,%2,%3}, [%4];"
                 : "=r"(r[0]), "=r"(r[1]), "=r"(r[2]), "=r"(r[3]) : "r"(addr));
}

__device__ __forceinline__ void mma16816(float* c, const uint32_t* a,
                                         const uint32_t* b) {
    asm volatile(
        "mma.sync.aligned.m16n8k16.row.col.f32.bf16.bf16.f32 "
        "{%0,%1,%2,%3}, {%4,%5,%6,%7}, {%8,%9}, {%0,%1,%2,%3};"
        : "+f"(c[0]), "+f"(c[1]), "+f"(c[2]), "+f"(c[3])
        : "r"(a[0]), "r"(a[1]), "r"(a[2]), "r"(a[3]), "r"(b[0]), "r"(b[1]));
}

__device__ __forceinline__ void cpa16(uint32_t dst, const void* src) {
    asm volatile("cp.async.cg.shared.global [%0], [%1], 16;"
                 :: "r"(dst), "l"(src));
}
#define CP_COMMIT() asm volatile("cp.async.commit_group;" ::: "memory")
#define CP_WAIT(n)  asm volatile("cp.async.wait_group %0;" :: "n"(n) : "memory")

__device__ __forceinline__ void split_f4(float4 v, uint2& hi, uint2& lo) {
    uint32_t u0 = __float_as_uint(v.x), u1 = __float_as_uint(v.y);
    uint32_t u2 = __float_as_uint(v.z), u3 = __float_as_uint(v.w);
    hi.x = (u0 >> 16) | (u1 & 0xFFFF0000u);
    hi.y = (u2 >> 16) | (u3 & 0xFFFF0000u);
    float l0 = v.x - __uint_as_float(u0 & 0xFFFF0000u);
    float l1 = v.y - __uint_as_float(u1 & 0xFFFF0000u);
    float l2 = v.z - __uint_as_float(u2 & 0xFFFF0000u);
    float l3 = v.w - __uint_as_float(u3 & 0xFFFF0000u);
    __nv_bfloat162 p01 = __floats2bfloat162_rn(l0, l1);
    __nv_bfloat162 p23 = __floats2bfloat162_rn(l2, l3);
    lo.x = *reinterpret_cast<uint32_t*>(&p01);
    lo.y = *reinterpret_cast<uint32_t*>(&p23);
}

__device__ __forceinline__ float norm_factor(float ssq_part, float scale) {
    float ssq = ssq_part;
    #pragma unroll
    for (int o = 16; o > 0; o >>= 1) ssq += __shfl_xor_sync(0xffffffffu, ssq, o);
    __shared__ float ws[8];
    int w = threadIdx.x >> 5, l = threadIdx.x & 31;
    if (l == 0) ws[w] = ssq;
    __syncthreads();
    if (w == 0) {
        float s = (l < 8) ? ws[l] : 0.0f;
        #pragma unroll
        for (int o = 4; o > 0; o >>= 1) s += __shfl_xor_sync(0xffffffffu, s, o);
        if (l == 0) ws[0] = s;
    }
    __syncthreads();
    return scale / fmaxf(sqrtf(ws[0]), 1e-5f);
}

// ===========================================================================
// scalenorm_x: x[4096,1024] -> row-major bf16 hi/lo
// ===========================================================================
__global__ __launch_bounds__(256) void scalenorm_x(
    const float* __restrict__ in, const float* __restrict__ scale_p,
    __nv_bfloat16* __restrict__ oh, __nv_bfloat16* __restrict__ ol)
{
    int r = blockIdx.x, t = threadIdx.x;
    float4 f = ((const float4*)in)[(size_t)r * 256 + t];
    float fac = norm_factor(f.x*f.x + f.y*f.y + f.z*f.z + f.w*f.w, scale_p[0]);
    f.x *= fac; f.y *= fac; f.z *= fac; f.w *= fac;
    uint2 hi, lo;
    split_f4(f, hi, lo);
    size_t off = (size_t)r * 1024 + t * 4;
    *(uint2*)((char*)oh + off * 2) = hi;
    *(uint2*)((char*)ol + off * 2) = lo;
}

// ===========================================================================
// scalenorm_qkv: z=0 q->slab hi/lo, z=1 k->slab hi/lo, z=2 v in place
// (flat slab layout == row-major layout, offsets identical)
// ===========================================================================
__global__ __launch_bounds__(256) void scalenorm_qkv(
    const float* __restrict__ q, const float* __restrict__ k,
    float* __restrict__ v, const float* __restrict__ scale_p,
    __nv_bfloat16* __restrict__ qh, __nv_bfloat16* __restrict__ ql,
    __nv_bfloat16* __restrict__ kh, __nv_bfloat16* __restrict__ kl)
{
    int z = blockIdx.y, r = blockIdx.x, t = threadIdx.x;
    const float* in = (z == 0) ? q : (z == 1) ? k : v;
    float4 f = ((const float4*)in)[(size_t)r * 256 + t];
    float fac = norm_factor(f.x*f.x + f.y*f.y + f.z*f.z + f.w*f.w, scale_p[0]);
    f.x *= fac; f.y *= fac; f.z *= fac; f.w *= fac;

    if (z == 2) { ((float4*)v)[(size_t)r * 256 + t] = f; return; }
    uint2 hi, lo;
    split_f4(f, hi, lo);
    size_t off = (size_t)r * 1024 + t * 4;
    if (z == 1) {
        *(uint2*)((char*)kh + off * 2) = hi;
        *(uint2*)((char*)kl + off * 2) = lo;
    } else {
        *(uint2*)((char*)qh + off * 2) = hi;
        *(uint2*)((char*)ql + off * 2) = lo;
    }
}

// ===========================================================================
// weight split
// ===========================================================================
__global__ __launch_bounds__(256) void wsplit(
    const float* __restrict__ w0, const float* __restrict__ w1,
    const float* __restrict__ w2,
    __nv_bfloat16* __restrict__ wh, __nv_bfloat16* __restrict__ wl)
{
    size_t idx = ((size_t)blockIdx.x * 256 + threadIdx.x) * 4;
    int which = (int)(idx >> 20);
    const float* src = (which == 0) ? w0 : (which == 1) ? w1 : w2;
    float4 f = *(const float4*)(src + (idx & 1048575));
    uint2 hi, lo;
    split_f4(f, hi, lo);
    *(uint2*)((char*)wh + idx * 2) = hi;
    *(uint2*)((char*)wl + idx * 2) = lo;
}

// ===========================================================================
// V^T + hi/lo split
// ===========================================================================
__global__ __launch_bounds__(256) void vt_convert(
    const float* __restrict__ v,
    __nv_bfloat16* __restrict__ vh, __nv_bfloat16* __restrict__ vl)
{
    int g  = blockIdx.z;
    int k0 = blockIdx.x * 64;
    const float* vg = v + (size_t)g * GRP_STRIDE;
    __shared__ float sm[64][68];
    int t = threadIdx.x;
    int kr = t >> 2, f4 = (t & 3) * 4;
    const float4* rp = (const float4*)(vg + (size_t)(k0 + kr) * DK);
    #pragma unroll
    for (int i = 0; i < 4; i++) {
        float4 f = rp[f4 + i];
        *(float4*)&sm[kr][(f4 + i) * 4] = f;
    }
    __syncthreads();
    int n = t >> 2;
    size_t ob = (size_t)g * (DK * TSEQ) + (size_t)n * TSEQ + k0;
    #pragma unroll
    for (int j = 0; j < 4; j++) {
        int kk = (t & 3) * 16 + j * 4;
        float4 f = make_float4(sm[kk+0][n], sm[kk+1][n], sm[kk+2][n], sm[kk+3][n]);
        uint2 hi, lo;
        split_f4(f, hi, lo);
        *(uint2*)((char*)vh + (ob + kk) * 2) = hi;
        *(uint2*)((char*)vl + (ob + kk) * 2) = lo;
    }
}

// ===========================================================================
// gemm_bb (unchanged from R7): BM=128, BN=128, BK=32, cp.async 3-stage
// ===========================================================================
#define NSTAGE  3
#define STG_SZ  32768
#define GB_SMEM (NSTAGE * STG_SZ)

__global__ __launch_bounds__(256, 2) void gemm_bb(
    int mode,
    const __nv_bfloat16* __restrict__ Ah, const __nv_bfloat16* __restrict__ Al,
    const __nv_bfloat16* __restrict__ Bh, const __nv_bfloat16* __restrict__ Bl,
    const float* __restrict__ bias0, const float* __restrict__ bias1,
    const float* __restrict__ bias2,
    float* __restrict__ C0, float* __restrict__ C1, float* __restrict__ C2,
    int lda, int ldb, int ldc, int K, float alpha)
{
    extern __shared__ char smx[];
    uint32_t sbase = smem_u32(smx);

    const float* bias;
    float* C;
    int z = blockIdx.z;
    if (mode == 0) {
        Bh += (size_t)z * 1048576;  Bl += (size_t)z * 1048576;
        bias = (z == 0) ? bias0 : (z == 1) ? bias1 : bias2;
        C    = (z == 0) ? C0    : (z == 1) ? C1    : C2;
    } else {
        Ah += (size_t)z * 131072;   Al += (size_t)z * 131072;
        Bh += (size_t)z * 131072;   Bl += (size_t)z * 131072;
        bias = nullptr;
        C = C0 + (size_t)z * (size_t)ATTN_PER_G;
    }
    int rowBase = blockIdx.y * 128, colBase = blockIdx.x * 128;
    int tid = threadIdx.x, lane = tid & 31, wid = tid >> 5;
    int wm = wid >> 2, wn = wid & 3;

    int lr = tid >> 1, half = tid & 1;
    uint32_t swz = (lr >> 1) & 3;
    uint32_t d0 = lr * 64 + (((2u * half + 0) ^ swz) << 4);
    uint32_t d1 = lr * 64 + (((2u * half + 1) ^ swz) << 4);
    const char* aSrcH = (const char*)(Ah + (size_t)(rowBase + lr) * lda + half * 16);
    const char* aSrcL = (const char*)(Al + (size_t)(rowBase + lr) * lda + half * 16);
    const char* bSrcH = (const char*)(Bh + (size_t)(colBase + lr) * ldb + half * 16);
    const char* bSrcL = (const char*)(Bl + (size_t)(colBase + lr) * ldb + half * 16);

    int NC = K >> 5;

    auto issue = [&](int c, int s) {
        uint32_t st = sbase + s * STG_SZ;
        size_t ko = (size_t)c * 64;
        cpa16(st +         d0, aSrcH + ko);
        cpa16(st +         d1, aSrcH + ko + 16);
        cpa16(st +  8192 + d0, aSrcL + ko);
        cpa16(st +  8192 + d1, aSrcL + ko + 16);
        cpa16(st + 16384 + d0, bSrcH + ko);
        cpa16(st + 16384 + d1, bSrcH + ko + 16);
        cpa16(st + 24576 + d0, bSrcL + ko);
        cpa16(st + 24576 + d1, bSrcL + ko + 16);
        CP_COMMIT();
    };

    issue(0, 0);
    if (NC > 1) issue(1, 1);

    float acc[4][4][4];
    #pragma unroll
    for (int a = 0; a < 4; a++)
        #pragma unroll
        for (int b = 0; b < 4; b++)
            #pragma unroll
            for (int r = 0; r < 4; r++) acc[a][b][r] = 0.0f;

    int stage = 0;
    for (int c = 0; c < NC; c++) {
        if (c < NC - 1) CP_WAIT(1); else CP_WAIT(0);
        __syncthreads();
        if (c + NSTAGE - 1 < NC)
            issue(c + NSTAGE - 1, (stage + NSTAGE - 1) % NSTAGE);

        uint32_t stA = sbase + stage * STG_SZ;
        uint32_t stB = stA + 16384;
        #pragma unroll
        for (int kk = 0; kk < 2; kk++) {
            uint32_t ah[4][4], al[4][4];
            #pragma unroll
            for (int mt = 0; mt < 4; mt++) {
                int r = wm * 64 + mt * 16 + (lane & 15);
                uint32_t c16 = kk * 2 + (lane >> 4);
                uint32_t off = r * 64 + ((c16 ^ ((r >> 1) & 3)) << 4);
                ldsm4(ah[mt], stA + off);
                ldsm4(al[mt], stA + 8192 + off);
            }
            uint32_t bh[2][4], bl[2][4];
            #pragma unroll
            for (int np = 0; np < 2; np++) {
                int r = wn * 32 + np * 16 + ((lane >> 4) << 3) + (lane & 7);
                uint32_t c16 = kk * 2 + ((lane >> 3) & 1);
                uint32_t off = r * 64 + ((c16 ^ ((r >> 1) & 3)) << 4);
                ldsm4(bh[np], stB + off);
                ldsm4(bl[np], stB + 8192 + off);
            }
            #pragma unroll
            for (int mt = 0; mt < 4; mt++)
                #pragma unroll
                for (int nt = 0; nt < 4; nt++) {
                    const uint32_t* ph = &bh[nt >> 1][(nt & 1) * 2];
                    const uint32_t* pl = &bl[nt >> 1][(nt & 1) * 2];
                    mma16816(acc[mt][nt], ah[mt], ph);
                    mma16816(acc[mt][nt], ah[mt], pl);
                    mma16816(acc[mt][nt], al[mt], ph);
                }
        }
        __syncthreads();
        stage = (stage + 1) % NSTAGE;
    }

    int r0 = rowBase + wm * 64 + (lane >> 2);
    int c0 = colBase + wn * 32 + (lane & 3) * 2;
    #pragma unroll
    for (int nt = 0; nt < 4; nt++) {
        int col = c0 + nt * 8;
        float b0 = 0.0f, b1 = 0.0f;
        if (bias) { b0 = bias[col]; b1 = bias[col + 1]; }
        #pragma unroll
        for (int mt = 0; mt < 4; mt++) {
            int row = r0 + mt * 16;
            *(float2*)(C + (size_t)row * ldc + col) =
                make_float2(acc[mt][nt][0] * alpha + b0,
                            acc[mt][nt][1] * alpha + b1);
            *(float2*)(C + (size_t)(row + 8) * ldc + col) =
                make_float2(acc[mt][nt][2] * alpha + b0,
                            acc[mt][nt][3] * alpha + b1);
        }
    }
}

// ===========================================================================
// pv_bb: O[g] = P[g] @ V[g]^T, all operands pre-split bf16, cp.async 3-stage.
// BM=128, BN=64, BK=32; 8 warps 4(m)x2(n), warp 32x32; 2 CTAs/SM.
// stage: Ah 8K | Al 8K | Bh 4K | Bl 4K = 24KB.
// Scatter epilogue (R3-validated): out[g,s,e] -> b=g>>4,
//   t=(g&15)*128 + 2e + (s>>10), d = s & 1023.
// ===========================================================================
#define PV_STG 24576
#define PVB_SMEM (NSTAGE * PV_STG)

__global__ __launch_bounds__(256, 2) void pv_bb(
    const __nv_bfloat16* __restrict__ Ph, const __nv_bfloat16* __restrict__ Pl,
    const __nv_bfloat16* __restrict__ Vh, const __nv_bfloat16* __restrict__ Vl,
    float* __restrict__ Out)
{
    extern __shared__ char smx[];
    uint32_t sbase = smem_u32(smx);

    int g = blockIdx.z;
    int rowBase = blockIdx.x * 128;
    const __nv_bfloat16* PhG = Ph + (size_t)g * ATTN_PER_G;
    const __nv_bfloat16* PlG = Pl + (size_t)g * ATTN_PER_G;
    const __nv_bfloat16* VhG = Vh + (size_t)g * (DK * TSEQ);
    const __nv_bfloat16* VlG = Vl + (size_t)g * (DK * TSEQ);

    int tid = threadIdx.x, lane = tid & 31, wid = tid >> 5;
    int wm = wid >> 1, wn = wid & 1;

    // A loader: 128 rows x 2 halves
    int lr = tid >> 1, half = tid & 1;
    uint32_t swz = (lr >> 1) & 3;
    uint32_t d0 = lr * 64 + (((2u * half + 0) ^ swz) << 4);
    uint32_t d1 = lr * 64 + (((2u * half + 1) ^ swz) << 4);
    const char* aSrcH = (const char*)(PhG + (size_t)(rowBase + lr) * TSEQ + half * 16);
    const char* aSrcL = (const char*)(PlG + (size_t)(rowBase + lr) * TSEQ + half * 16);

    // B loader: first 128 threads, 64 rows x 2 halves
    int br = (tid & 127) >> 1;
    int bhf = tid & 1;
    uint32_t bswz = (br >> 1) & 3;
    uint32_t e0 = br * 64 + (((2u * bhf + 0) ^ bswz) << 4);
    uint32_t e1 = br * 64 + (((2u * bhf + 1) ^ bswz) << 4);
    const char* bSrcH = (const char*)(VhG + (size_t)br * TSEQ + bhf * 16);
    const char* bSrcL = (const char*)(VlG + (size_t)br * TSEQ + bhf * 16);

    const int NC = TSEQ >> 5;   // 64

    auto issue = [&](int c, int s) {
        uint32_t st = sbase + s * PV_STG;
        size_t ko = (size_t)c * 64;
        cpa16(st +        d0, aSrcH + ko);
        cpa16(st +        d1, aSrcH + ko + 16);
        cpa16(st + 8192 + d0, aSrcL + ko);
        cpa16(st + 8192 + d1, aSrcL + ko + 16);
        if (tid < 128) {
            cpa16(st + 16384 + e0, bSrcH + ko);
            cpa16(st + 16384 + e1, bSrcH + ko + 16);
            cpa16(st + 20480 + e0, bSrcL + ko);
            cpa16(st + 20480 + e1, bSrcL + ko + 16);
        }
        CP_COMMIT();
    };

    issue(0, 0);
    issue(1, 1);

    float acc[2][4][4];
    #pragma unroll
    for (int a = 0; a < 2; a++)
        #pragma unroll
        for (int b = 0; b < 4; b++)
            #pragma unroll
            for (int r = 0; r < 4; r++) acc[a][b][r] = 0.0f;

    int stage = 0;
    for (int c = 0; c < NC; c++) {
        if (c < NC - 1) CP_WAIT(1); else CP_WAIT(0);
        __syncthreads();
        if (c + NSTAGE - 1 < NC)
            issue(c + NSTAGE - 1, (stage + NSTAGE - 1) % NSTAGE);

        uint32_t stA = sbase + stage * PV_STG;
        uint32_t stB = stA + 16384;
        #pragma unroll
        for (int kk = 0; kk < 2; kk++) {
            uint32_t ah[2][4], al[2][4];
            #pragma unroll
            for (int mt = 0; mt < 2; mt++) {
                int r = wm * 32 + mt * 16 + (lane & 15);
                uint32_t c16 = kk * 2 + (lane >> 4);
                uint32_t off = r * 64 + ((c16 ^ ((r >> 1) & 3)) << 4);
                ldsm4(ah[mt], stA + off);
                ldsm4(al[mt], stA + 8192 + off);
            }
            uint32_t bh[2][4], bl[2][4];
            #pragma unroll
            for (int np = 0; np < 2; np++) {
                int r = wn * 32 + np * 16 + ((lane >> 4) << 3) + (lane & 7);
                uint32_t c16 = kk * 2 + ((lane >> 3) & 1);
                uint32_t off = r * 64 + ((c16 ^ ((r >> 1) & 3)) << 4);
                ldsm4(bh[np], stB + off);
                ldsm4(bl[np], stB + 4096 + off);
            }
            #pragma unroll
            for (int mt = 0; mt < 2; mt++)
                #pragma unroll
                for (int nt = 0; nt < 4; nt++) {
                    const uint32_t* ph = &bh[nt >> 1][(nt & 1) * 2];
                    const uint32_t* pl = &bl[nt >> 1][(nt & 1) * 2];
                    mma16816(acc[mt][nt], ah[mt], ph);
                    mma16816(acc[mt][nt], ah[mt], pl);
                    mma16816(acc[mt][nt], al[mt], ph);
                }
        }
        __syncthreads();
        stage = (stage + 1) % NSTAGE;
    }

    // scatter epilogue (validated mapping)
    int b  = g >> 4;
    int gg = g & 15;
    float* ob = Out + (size_t)b * 2097152;
    int rr  = rowBase + wm * 32 + (lane >> 2);
    int en0 = wn * 32 + (lane & 3) * 2;
    #pragma unroll
    for (int mt = 0; mt < 2; mt++) {
        #pragma unroll
        for (int hf = 0; hf < 2; hf++) {
            int s   = rr + mt * 16 + hf * 8;
            int thi = s >> 10;
            int d   = s & 1023;
            #pragma unroll
            for (int nt = 0; nt < 4; nt++) {
                int e  = en0 + nt * 8;
                int t0 = gg * 128 + 2 * e + thi;
                int t1 = gg * 128 + 2 * (e + 1) + thi;
                ob[(size_t)t0 * 1024 + d] = acc[mt][nt][hf * 2 + 0];
                ob[(size_t)t1 * 1024 + d] = acc[mt][nt][hf * 2 + 1];
            }
        }
    }
}

// ===========================================================================
// Row softmax in place + emit P as bf16 hi/lo
// ===========================================================================
__global__ __launch_bounds__(256) void softmax_kernel(
    float* __restrict__ attn,
    __nv_bfloat16* __restrict__ ph, __nv_bfloat16* __restrict__ pl)
{
    size_t row = blockIdx.x;
    float4* p = (float4*)attn + row * (TSEQ / 4);
    int tid = threadIdx.x;

    float4 a = p[tid];
    float4 b = p[tid + 256];

    float m = fmaxf(fmaxf(fmaxf(a.x, a.y), fmaxf(a.z, a.w)),
                    fmaxf(fmaxf(b.x, b.y), fmaxf(b.z, b.w)));
    #pragma unroll
    for (int o = 16; o > 0; o >>= 1) m = fmaxf(m, __shfl_xor_sync(0xffffffffu, m, o));

    __shared__ float ws[8];
    int w = tid >> 5, l = tid & 31;
    if (l == 0) ws[w] = m;
    __syncthreads();
    if (w == 0) {
        float s = (l < 8) ? ws[l] : -3.4e38f;
        #pragma unroll
        for (int o = 4; o > 0; o >>= 1) s = fmaxf(s, __shfl_xor_sync(0xffffffffu, s, o));
        if (l == 0) ws[0] = s;
    }
    __syncthreads();
    m = ws[0];
    __syncthreads();

    a.x = __expf(a.x - m); a.y = __expf(a.y - m);
    a.z = __expf(a.z - m); a.w = __expf(a.w - m);
    b.x = __expf(b.x - m); b.y = __expf(b.y - m);
    b.z = __expf(b.z - m); b.w = __expf(b.w - m);

    float ssum = a.x + a.y + a.z + a.w + b.x + b.y + b.z + b.w;
    #pragma unroll
    for (int o = 16; o > 0; o >>= 1) ssum += __shfl_xor_sync(0xffffffffu, ssum, o);
    if (l == 0) ws[w] = ssum;
    __syncthreads();
    if (w == 0) {
        float s = (l < 8) ? ws[l] : 0.0f;
        #pragma unroll
        for (int o = 4; o > 0; o >>= 1) s += __shfl_xor_sync(0xffffffffu, s, o);
        if (l == 0) ws[0] = s;
    }
    __syncthreads();
    float inv = 1.0f / ws[0];

    a.x *= inv; a.y *= inv; a.z *= inv; a.w *= inv;
    b.x *= inv; b.y *= inv; b.z *= inv; b.w *= inv;
    p[tid]       = a;
    p[tid + 256] = b;

    uint2 h1, l1, h2, l2;
    split_f4(a, h1, l1);
    split_f4(b, h2, l2);
    size_t off = row * TSEQ + tid * 4;
    *(uint2*)((char*)ph + off * 2) = h1;
    *(uint2*)((char*)pl + off * 2) = l1;
    off += 1024;
    *(uint2*)((char*)ph + off * 2) = h2;
    *(uint2*)((char*)pl + off * 2) = l2;
}

// ===========================================================================
// kernel_launch
// ===========================================================================
extern "C" void kernel_launch(void* const* d_in, const int* in_sizes, int n_in,
                              void* d_out, int out_size)
{
    const float* x  = (const float*)d_in[0];
    const float* sc = (const float*)d_in[1];
    const float* wq = (const float*)d_in[2];
    const float* bq = (const float*)d_in[3];
    const float* wk = (const float*)d_in[4];
    const float* bk = (const float*)d_in[5];
    const float* wv = (const float*)d_in[6];
    const float* bv = (const float*)d_in[7];

    float* out  = (float*)d_out;
    float* attn = out + OUT_ELEMS;

    float *q, *k, *v;
    __nv_bfloat16 *xh, *xl, *qh, *ql, *kh, *kl, *wh, *wl, *vh, *vl, *ph, *pl;
    cudaGetSymbolAddress((void**)&q,  g_q);
    cudaGetSymbolAddress((void**)&k,  g_k);
    cudaGetSymbolAddress((void**)&v,  g_v);
    cudaGetSymbolAddress((void**)&xh, g_xh);
    cudaGetSymbolAddress((void**)&xl, g_xl);
    cudaGetSymbolAddress((void**)&qh, g_qh);
    cudaGetSymbolAddress((void**)&ql, g_ql);
    cudaGetSymbolAddress((void**)&kh, g_kh);
    cudaGetSymbolAddress((void**)&kl, g_kl);
    cudaGetSymbolAddress((void**)&wh, g_wh);
    cudaGetSymbolAddress((void**)&wl, g_wl);
    cudaGetSymbolAddress((void**)&vh, g_vh);
    cudaGetSymbolAddress((void**)&vl, g_vl);
    cudaGetSymbolAddress((void**)&ph, g_ph);
    cudaGetSymbolAddress((void**)&pl, g_pl);

    cudaFuncSetAttribute(gemm_bb, cudaFuncAttributeMaxDynamicSharedMemorySize, GB_SMEM);
    cudaFuncSetAttribute(pv_bb,   cudaFuncAttributeMaxDynamicSharedMemorySize, PVB_SMEM);

    // 1) normalize x -> row-major hi/lo; split weights
    scalenorm_x<<<ROWS, 256>>>(x, sc, xh, xl);
    wsplit<<<3072, 256>>>(wq, wk, wv, wh, wl);

    // 2) projections (batched)
    gemm_bb<<<dim3(8, 32, 3), 256, GB_SMEM>>>(
        0, xh, xl, wh, wl, bq, bk, bv, q, k, v,
        DMODEL, DMODEL, DMODEL, DMODEL, 1.0f);

    // 3) scale_norm q/k/v
    scalenorm_qkv<<<dim3(ROWS, 3), 256>>>(q, k, v, sc, qh, ql, kh, kl);

    // 3b) V^T hi/lo split
    vt_convert<<<dim3(TSEQ / 64, 1, NGRP), 256>>>(v, vh, vl);

    // 4) S = Q K^T / 8 into attn region
    gemm_bb<<<dim3(16, 16, NGRP), 256, GB_SMEM>>>(
        1, qh, ql, kh, kl, nullptr, nullptr, nullptr, attn, nullptr, nullptr,
        DK, DK, TSEQ, DK, 0.125f);

    // 5) softmax in place + emit bf16 P hi/lo
    softmax_kernel<<<NGRP * TSEQ, 256>>>(attn, ph, pl);

    // 6) O = P @ V (pipelined bf16 GEMM, scatter epilogue)
    pv_bb<<<dim3(TSEQ / 128, 1, NGRP), 256, PVB_SMEM>>>(ph, pl, vh, vl, out);
}

// round 9
// speedup vs baseline: 1.0444x; 1.0444x over previous
#include <cuda_runtime.h>
#include <cuda_bf16.h>
#include <math.h>
#include <stdint.h>

#define ROWS   4096
#define DMODEL 1024
#define TSEQ   2048
#define DK     64
#define NGRP   32
#define OUT_ELEMS 4194304
#define ATTN_PER_G 4194304
#define GRP_STRIDE 131072

// Scratch
__device__ float g_q[ROWS * DMODEL];
__device__ float g_k[ROWS * DMODEL];
__device__ float g_v[ROWS * DMODEL];
__device__ __nv_bfloat16 g_xh[ROWS * DMODEL], g_xl[ROWS * DMODEL];
__device__ __nv_bfloat16 g_qh[ROWS * DMODEL], g_ql[ROWS * DMODEL];
__device__ __nv_bfloat16 g_kh[ROWS * DMODEL], g_kl[ROWS * DMODEL];
__device__ __nv_bfloat16 g_wh[3 * DMODEL * DMODEL], g_wl[3 * DMODEL * DMODEL];
__device__ __nv_bfloat16 g_vh[NGRP * DK * TSEQ], g_vl[NGRP * DK * TSEQ];

// ===========================================================================
__device__ __forceinline__ uint32_t smem_u32(const void* p) {
    uint32_t a;
    asm("{ .reg .u64 t; cvta.to.shared.u64 t, %1; cvt.u32.u64 %0, t; }"
        : "=r"(a) : "l"(p));
    return a;
}

__device__ __forceinline__ void ldsm4(uint32_t* r, uint32_t addr) {
    asm volatile("ldmatrix.sync.aligned.m8n8.x4.shared.b16 {%0,%1,%2,%3}, [%4];"
                 : "=r"(r[0]), "=r"(r[1]), "=r"(r[2]), "=r"(r[3]) : "r"(addr));
}

__device__ __forceinline__ void mma16816(float* c, const uint32_t* a,
                                         const uint32_t* b) {
    asm volatile(
        "mma.sync.aligned.m16n8k16.row.col.f32.bf16.bf16.f32 "
        "{%0,%1,%2,%3}, {%4,%5,%6,%7}, {%8,%9}, {%0,%1,%2,%3};"
        : "+f"(c[0]), "+f"(c[1]), "+f"(c[2]), "+f"(c[3])
        : "r"(a[0]), "r"(a[1]), "r"(a[2]), "r"(a[3]), "r"(b[0]), "r"(b[1]));
}

__device__ __forceinline__ void cpa16(uint32_t dst, const void* src) {
    asm volatile("cp.async.cg.shared.global [%0], [%1], 16;"
                 :: "r"(dst), "l"(src));
}
#define CP_COMMIT() asm volatile("cp.async.commit_group;" ::: "memory")
#define CP_WAIT(n)  asm volatile("cp.async.wait_group %0;" :: "n"(n) : "memory")

__device__ __forceinline__ void split_f4(float4 v, uint2& hi, uint2& lo) {
    uint32_t u0 = __float_as_uint(v.x), u1 = __float_as_uint(v.y);
    uint32_t u2 = __float_as_uint(v.z), u3 = __float_as_uint(v.w);
    hi.x = (u0 >> 16) | (u1 & 0xFFFF0000u);
    hi.y = (u2 >> 16) | (u3 & 0xFFFF0000u);
    float l0 = v.x - __uint_as_float(u0 & 0xFFFF0000u);
    float l1 = v.y - __uint_as_float(u1 & 0xFFFF0000u);
    float l2 = v.z - __uint_as_float(u2 & 0xFFFF0000u);
    float l3 = v.w - __uint_as_float(u3 & 0xFFFF0000u);
    __nv_bfloat162 p01 = __floats2bfloat162_rn(l0, l1);
    __nv_bfloat162 p23 = __floats2bfloat162_rn(l2, l3);
    lo.x = *reinterpret_cast<uint32_t*>(&p01);
    lo.y = *reinterpret_cast<uint32_t*>(&p23);
}

__device__ __forceinline__ float norm_factor(float ssq_part, float scale) {
    float ssq = ssq_part;
    #pragma unroll
    for (int o = 16; o > 0; o >>= 1) ssq += __shfl_xor_sync(0xffffffffu, ssq, o);
    __shared__ float ws[8];
    int w = threadIdx.x >> 5, l = threadIdx.x & 31;
    if (l == 0) ws[w] = ssq;
    __syncthreads();
    if (w == 0) {
        float s = (l < 8) ? ws[l] : 0.0f;
        #pragma unroll
        for (int o = 4; o > 0; o >>= 1) s += __shfl_xor_sync(0xffffffffu, s, o);
        if (l == 0) ws[0] = s;
    }
    __syncthreads();
    return scale / fmaxf(sqrtf(ws[0]), 1e-5f);
}

// ===========================================================================
// scalenorm_x: x[4096,1024] -> row-major bf16 hi/lo
// ===========================================================================
__global__ __launch_bounds__(256) void scalenorm_x(
    const float* __restrict__ in, const float* __restrict__ scale_p,
    __nv_bfloat16* __restrict__ oh, __nv_bfloat16* __restrict__ ol)
{
    int r = blockIdx.x, t = threadIdx.x;
    float4 f = ((const float4*)in)[(size_t)r * 256 + t];
    float fac = norm_factor(f.x*f.x + f.y*f.y + f.z*f.z + f.w*f.w, scale_p[0]);
    f.x *= fac; f.y *= fac; f.z *= fac; f.w *= fac;
    uint2 hi, lo;
    split_f4(f, hi, lo);
    size_t off = (size_t)r * 1024 + t * 4;
    *(uint2*)((char*)oh + off * 2) = hi;
    *(uint2*)((char*)ol + off * 2) = lo;
}

// ===========================================================================
// scalenorm_qkv: z=0 q->slab hi/lo, z=1 k->slab hi/lo, z=2 v in place
// ===========================================================================
__global__ __launch_bounds__(256) void scalenorm_qkv(
    const float* __restrict__ q, const float* __restrict__ k,
    float* __restrict__ v, const float* __restrict__ scale_p,
    __nv_bfloat16* __restrict__ qh, __nv_bfloat16* __restrict__ ql,
    __nv_bfloat16* __restrict__ kh, __nv_bfloat16* __restrict__ kl)
{
    int z = blockIdx.y, r = blockIdx.x, t = threadIdx.x;
    const float* in = (z == 0) ? q : (z == 1) ? k : v;
    float4 f = ((const float4*)in)[(size_t)r * 256 + t];
    float fac = norm_factor(f.x*f.x + f.y*f.y + f.z*f.z + f.w*f.w, scale_p[0]);
    f.x *= fac; f.y *= fac; f.z *= fac; f.w *= fac;

    if (z == 2) { ((float4*)v)[(size_t)r * 256 + t] = f; return; }
    uint2 hi, lo;
    split_f4(f, hi, lo);
    size_t off = (size_t)r * 1024 + t * 4;
    if (z == 1) {
        *(uint2*)((char*)kh + off * 2) = hi;
        *(uint2*)((char*)kl + off * 2) = lo;
    } else {
        *(uint2*)((char*)qh + off * 2) = hi;
        *(uint2*)((char*)ql + off * 2) = lo;
    }
}

// ===========================================================================
// weight split
// ===========================================================================
__global__ __launch_bounds__(256) void wsplit(
    const float* __restrict__ w0, const float* __restrict__ w1,
    const float* __restrict__ w2,
    __nv_bfloat16* __restrict__ wh, __nv_bfloat16* __restrict__ wl)
{
    size_t idx = ((size_t)blockIdx.x * 256 + threadIdx.x) * 4;
    int which = (int)(idx >> 20);
    const float* src = (which == 0) ? w0 : (which == 1) ? w1 : w2;
    float4 f = *(const float4*)(src + (idx & 1048575));
    uint2 hi, lo;
    split_f4(f, hi, lo);
    *(uint2*)((char*)wh + idx * 2) = hi;
    *(uint2*)((char*)wl + idx * 2) = lo;
}

// ===========================================================================
// V^T + hi/lo split
// ===========================================================================
__global__ __launch_bounds__(256) void vt_convert(
    const float* __restrict__ v,
    __nv_bfloat16* __restrict__ vh, __nv_bfloat16* __restrict__ vl)
{
    int g  = blockIdx.z;
    int k0 = blockIdx.x * 64;
    const float* vg = v + (size_t)g * GRP_STRIDE;
    __shared__ float sm[64][68];
    int t = threadIdx.x;
    int kr = t >> 2, f4 = (t & 3) * 4;
    const float4* rp = (const float4*)(vg + (size_t)(k0 + kr) * DK);
    #pragma unroll
    for (int i = 0; i < 4; i++) {
        float4 f = rp[f4 + i];
        *(float4*)&sm[kr][(f4 + i) * 4] = f;
    }
    __syncthreads();
    int n = t >> 2;
    size_t ob = (size_t)g * (DK * TSEQ) + (size_t)n * TSEQ + k0;
    #pragma unroll
    for (int j = 0; j < 4; j++) {
        int kk = (t & 3) * 16 + j * 4;
        float4 f = make_float4(sm[kk+0][n], sm[kk+1][n], sm[kk+2][n], sm[kk+3][n]);
        uint2 hi, lo;
        split_f4(f, hi, lo);
        *(uint2*)((char*)vh + (ob + kk) * 2) = hi;
        *(uint2*)((char*)vl + (ob + kk) * 2) = lo;
    }
}

// ===========================================================================
// gemm_bb (unchanged R7): BM=128, BN=128, BK=32, cp.async 3-stage
// ===========================================================================
#define NSTAGE  3
#define STG_SZ  32768
#define GB_SMEM (NSTAGE * STG_SZ)

__global__ __launch_bounds__(256, 2) void gemm_bb(
    int mode,
    const __nv_bfloat16* __restrict__ Ah, const __nv_bfloat16* __restrict__ Al,
    const __nv_bfloat16* __restrict__ Bh, const __nv_bfloat16* __restrict__ Bl,
    const float* __restrict__ bias0, const float* __restrict__ bias1,
    const float* __restrict__ bias2,
    float* __restrict__ C0, float* __restrict__ C1, float* __restrict__ C2,
    int lda, int ldb, int ldc, int K, float alpha)
{
    extern __shared__ char smx[];
    uint32_t sbase = smem_u32(smx);

    const float* bias;
    float* C;
    int z = blockIdx.z;
    if (mode == 0) {
        Bh += (size_t)z * 1048576;  Bl += (size_t)z * 1048576;
        bias = (z == 0) ? bias0 : (z == 1) ? bias1 : bias2;
        C    = (z == 0) ? C0    : (z == 1) ? C1    : C2;
    } else {
        Ah += (size_t)z * 131072;   Al += (size_t)z * 131072;
        Bh += (size_t)z * 131072;   Bl += (size_t)z * 131072;
        bias = nullptr;
        C = C0 + (size_t)z * (size_t)ATTN_PER_G;
    }
    int rowBase = blockIdx.y * 128, colBase = blockIdx.x * 128;
    int tid = threadIdx.x, lane = tid & 31, wid = tid >> 5;
    int wm = wid >> 2, wn = wid & 3;

    int lr = tid >> 1, half = tid & 1;
    uint32_t swz = (lr >> 1) & 3;
    uint32_t d0 = lr * 64 + (((2u * half + 0) ^ swz) << 4);
    uint32_t d1 = lr * 64 + (((2u * half + 1) ^ swz) << 4);
    const char* aSrcH = (const char*)(Ah + (size_t)(rowBase + lr) * lda + half * 16);
    const char* aSrcL = (const char*)(Al + (size_t)(rowBase + lr) * lda + half * 16);
    const char* bSrcH = (const char*)(Bh + (size_t)(colBase + lr) * ldb + half * 16);
    const char* bSrcL = (const char*)(Bl + (size_t)(colBase + lr) * ldb + half * 16);

    int NC = K >> 5;

    auto issue = [&](int c, int s) {
        uint32_t st = sbase + s * STG_SZ;
        size_t ko = (size_t)c * 64;
        cpa16(st +         d0, aSrcH + ko);
        cpa16(st +         d1, aSrcH + ko + 16);
        cpa16(st +  8192 + d0, aSrcL + ko);
        cpa16(st +  8192 + d1, aSrcL + ko + 16);
        cpa16(st + 16384 + d0, bSrcH + ko);
        cpa16(st + 16384 + d1, bSrcH + ko + 16);
        cpa16(st + 24576 + d0, bSrcL + ko);
        cpa16(st + 24576 + d1, bSrcL + ko + 16);
        CP_COMMIT();
    };

    issue(0, 0);
    if (NC > 1) issue(1, 1);

    float acc[4][4][4];
    #pragma unroll
    for (int a = 0; a < 4; a++)
        #pragma unroll
        for (int b = 0; b < 4; b++)
            #pragma unroll
            for (int r = 0; r < 4; r++) acc[a][b][r] = 0.0f;

    int stage = 0;
    for (int c = 0; c < NC; c++) {
        if (c < NC - 1) CP_WAIT(1); else CP_WAIT(0);
        __syncthreads();
        if (c + NSTAGE - 1 < NC)
            issue(c + NSTAGE - 1, (stage + NSTAGE - 1) % NSTAGE);

        uint32_t stA = sbase + stage * STG_SZ;
        uint32_t stB = stA + 16384;
        #pragma unroll
        for (int kk = 0; kk < 2; kk++) {
            uint32_t ah[4][4], al[4][4];
            #pragma unroll
            for (int mt = 0; mt < 4; mt++) {
                int r = wm * 64 + mt * 16 + (lane & 15);
                uint32_t c16 = kk * 2 + (lane >> 4);
                uint32_t off = r * 64 + ((c16 ^ ((r >> 1) & 3)) << 4);
                ldsm4(ah[mt], stA + off);
                ldsm4(al[mt], stA + 8192 + off);
            }
            uint32_t bh[2][4], bl[2][4];
            #pragma unroll
            for (int np = 0; np < 2; np++) {
                int r = wn * 32 + np * 16 + ((lane >> 4) << 3) + (lane & 7);
                uint32_t c16 = kk * 2 + ((lane >> 3) & 1);
                uint32_t off = r * 64 + ((c16 ^ ((r >> 1) & 3)) << 4);
                ldsm4(bh[np], stB + off);
                ldsm4(bl[np], stB + 8192 + off);
            }
            #pragma unroll
            for (int mt = 0; mt < 4; mt++)
                #pragma unroll
                for (int nt = 0; nt < 4; nt++) {
                    const uint32_t* ph = &bh[nt >> 1][(nt & 1) * 2];
                    const uint32_t* pl = &bl[nt >> 1][(nt & 1) * 2];
                    mma16816(acc[mt][nt], ah[mt], ph);
                    mma16816(acc[mt][nt], ah[mt], pl);
                    mma16816(acc[mt][nt], al[mt], ph);
                }
        }
        __syncthreads();
        stage = (stage + 1) % NSTAGE;
    }

    int r0 = rowBase + wm * 64 + (lane >> 2);
    int c0 = colBase + wn * 32 + (lane & 3) * 2;
    #pragma unroll
    for (int nt = 0; nt < 4; nt++) {
        int col = c0 + nt * 8;
        float b0 = 0.0f, b1 = 0.0f;
        if (bias) { b0 = bias[col]; b1 = bias[col + 1]; }
        #pragma unroll
        for (int mt = 0; mt < 4; mt++) {
            int row = r0 + mt * 16;
            *(float2*)(C + (size_t)row * ldc + col) =
                make_float2(acc[mt][nt][0] * alpha + b0,
                            acc[mt][nt][1] * alpha + b1);
            *(float2*)(C + (size_t)(row + 8) * ldc + col) =
                make_float2(acc[mt][nt][2] * alpha + b0,
                            acc[mt][nt][3] * alpha + b1);
        }
    }
}

// ===========================================================================
// pv_fuse: per (g, 128-row block):
//   pass 1: online row max/sum over S (raw logits in attn region)
//   pass 2: per 32-col chunk: p = exp(v-m)*inv; write normalized attn;
//           split to bf16 hi/lo -> swizzled smem; MMA with V^T tiles.
// Scatter epilogue -> out (validated mapping).
// smem: S 3x16K | V 3x(4K+4K) | Aconv 2x16K | m/inv 1K  = 105KB
// ===========================================================================
#define PVF_S_OFF   0
#define PVF_V_OFF   49152
#define PVF_A_OFF   73728
#define PVF_M_OFF   106496
#define PVF_SMEM    107520

__global__ __launch_bounds__(256, 2) void pv_fuse(
    float* __restrict__ attn,
    const __nv_bfloat16* __restrict__ Vh, const __nv_bfloat16* __restrict__ Vl,
    float* __restrict__ Out)
{
    extern __shared__ char smx[];
    uint32_t sbase = smem_u32(smx);
    float* sm_m   = (float*)(smx + PVF_M_OFF);
    float* sm_inv = (float*)(smx + PVF_M_OFF + 512);

    int g = blockIdx.z;
    int rowBase = blockIdx.x * 128;
    float* Sg = attn + (size_t)g * ATTN_PER_G;
    const __nv_bfloat16* VhG = Vh + (size_t)g * (DK * TSEQ);
    const __nv_bfloat16* VlG = Vl + (size_t)g * (DK * TSEQ);

    int tid = threadIdx.x, lane = tid & 31, wid = tid >> 5;
    int wm = wid >> 1, wn = wid & 1;

    // ---- loaders ----
    // S: 1024 16B chunks/stage; thread does 4 (id = tid + t*256)
    // V: tid<128: br = tid>>1, bhf = tid&1 (pv_bb layout)
    int br = tid >> 1, bhf = tid & 1;
    uint32_t bswz = (br >> 1) & 3;
    uint32_t e0 = br * 64 + (((2u * bhf + 0) ^ bswz) << 4);
    uint32_t e1 = br * 64 + (((2u * bhf + 1) ^ bswz) << 4);
    const char* bSrcH = (const char*)(VhG + (size_t)br * TSEQ + bhf * 16);
    const char* bSrcL = (const char*)(VlG + (size_t)br * TSEQ + bhf * 16);

    auto issue = [&](int c, int s) {
        uint32_t stS = sbase + PVF_S_OFF + s * 16384;
        #pragma unroll
        for (int t4 = 0; t4 < 4; t4++) {
            int id = tid + t4 * 256;
            int r = id >> 3, c16 = id & 7;
            cpa16(stS + r * 128 + c16 * 16,
                  (const char*)(Sg + (size_t)(rowBase + r) * TSEQ) + c * 128 + c16 * 16);
        }
        if (tid < 128) {
            uint32_t stV = sbase + PVF_V_OFF + s * 8192;
            size_t ko = (size_t)c * 64;
            cpa16(stV +        e0, bSrcH + ko);
            cpa16(stV +        e1, bSrcH + ko + 16);
            cpa16(stV + 4096 + e0, bSrcL + ko);
            cpa16(stV + 4096 + e1, bSrcL + ko + 16);
        }
        CP_COMMIT();
    };

    issue(0, 0);
    issue(1, 1);

    // ---- pass 1: online max/sum per row (warp per row) ----
    for (int i = 0; i < 16; i++) {
        int r = wid * 16 + i;
        const float4* rp = (const float4*)(Sg + (size_t)(rowBase + r) * TSEQ) + lane;
        float m = -3.4e38f, s = 0.0f;
        #pragma unroll 4
        for (int j = 0; j < 16; j++) {
            float4 f = rp[j * 32];
            float c = fmaxf(fmaxf(f.x, f.y), fmaxf(f.z, f.w));
            if (c > m) { s *= __expf(m - c); m = c; }
            s += __expf(f.x - m) + __expf(f.y - m)
               + __expf(f.z - m) + __expf(f.w - m);
        }
        #pragma unroll
        for (int o = 16; o > 0; o >>= 1) {
            float m2 = __shfl_xor_sync(0xffffffffu, m, o);
            float s2 = __shfl_xor_sync(0xffffffffu, s, o);
            float mn = fmaxf(m, m2);
            s = s * __expf(m - mn) + s2 * __expf(m2 - mn);
            m = mn;
        }
        if (lane == 0) { sm_m[r] = m; sm_inv[r] = 1.0f / s; }
    }
    __syncthreads();

    // ---- pass 2: chunk loop ----
    float acc[2][4][4];
    #pragma unroll
    for (int a = 0; a < 2; a++)
        #pragma unroll
        for (int b = 0; b < 4; b++)
            #pragma unroll
            for (int r = 0; r < 4; r++) acc[a][b][r] = 0.0f;

    const int NC = TSEQ >> 5;   // 64
    int stage = 0;
    for (int c = 0; c < NC; c++) {
        if (c < NC - 1) CP_WAIT(1); else CP_WAIT(0);
        __syncthreads();
        if (c + 2 < NC) issue(c + 2, (stage + 2) % NSTAGE);

        uint32_t stS = sbase + PVF_S_OFF + stage * 16384;
        char* conv = smx + PVF_A_OFF + (c & 1) * 16384;

        // compute: p = exp(v-m)*inv; write attn; store bf16 hi/lo to conv
        #pragma unroll
        for (int it = 0; it < 4; it++) {
            int r  = (tid >> 3) + it * 32;
            int c4 = tid & 7;
            float4 f = *(float4*)(smx + PVF_S_OFF + stage * 16384 + r * 128 + c4 * 16);
            float mm = sm_m[r], iv = sm_inv[r];
            float4 p;
            p.x = __expf(f.x - mm) * iv;
            p.y = __expf(f.y - mm) * iv;
            p.z = __expf(f.z - mm) * iv;
            p.w = __expf(f.w - mm) * iv;
            *(float4*)(Sg + (size_t)(rowBase + r) * TSEQ + c * 32 + c4 * 4) = p;
            uint2 h, l;
            split_f4(p, h, l);
            uint32_t c16h = (uint32_t)(c4 >> 1);
            uint32_t sub  = (c4 & 1) * 8;
            uint32_t aoff = r * 64 + ((c16h ^ ((r >> 1) & 3)) << 4) + sub;
            *(uint2*)(conv +        aoff) = h;
            *(uint2*)(conv + 8192 + aoff) = l;
        }
        __syncthreads();

        // MMA phase (pv_bb-validated)
        uint32_t stA = sbase + PVF_A_OFF + (c & 1) * 16384;
        uint32_t stB = sbase + PVF_V_OFF + stage * 8192;
        #pragma unroll
        for (int kk = 0; kk < 2; kk++) {
            uint32_t ah[2][4], al[2][4];
            #pragma unroll
            for (int mt = 0; mt < 2; mt++) {
                int r = wm * 32 + mt * 16 + (lane & 15);
                uint32_t c16 = kk * 2 + (lane >> 4);
                uint32_t off = r * 64 + ((c16 ^ ((r >> 1) & 3)) << 4);
                ldsm4(ah[mt], stA + off);
                ldsm4(al[mt], stA + 8192 + off);
            }
            uint32_t bh[2][4], bl[2][4];
            #pragma unroll
            for (int np = 0; np < 2; np++) {
                int r = wn * 32 + np * 16 + ((lane >> 4) << 3) + (lane & 7);
                uint32_t c16 = kk * 2 + ((lane >> 3) & 1);
                uint32_t off = r * 64 + ((c16 ^ ((r >> 1) & 3)) << 4);
                ldsm4(bh[np], stB + off);
                ldsm4(bl[np], stB + 4096 + off);
            }
            #pragma unroll
            for (int mt = 0; mt < 2; mt++)
                #pragma unroll
                for (int nt = 0; nt < 4; nt++) {
                    const uint32_t* ph = &bh[nt >> 1][(nt & 1) * 2];
                    const uint32_t* pl = &bl[nt >> 1][(nt & 1) * 2];
                    mma16816(acc[mt][nt], ah[mt], ph);
                    mma16816(acc[mt][nt], ah[mt], pl);
                    mma16816(acc[mt][nt], al[mt], ph);
                }
        }
        stage = (stage + 1) % NSTAGE;
    }

    // scatter epilogue (validated)
    int b  = g >> 4;
    int gg = g & 15;
    float* ob = Out + (size_t)b * 2097152;
    int rr  = rowBase + wm * 32 + (lane >> 2);
    int en0 = wn * 32 + (lane & 3) * 2;
    #pragma unroll
    for (int mt = 0; mt < 2; mt++) {
        #pragma unroll
        for (int hf = 0; hf < 2; hf++) {
            int s   = rr + mt * 16 + hf * 8;
            int thi = s >> 10;
            int d   = s & 1023;
            #pragma unroll
            for (int nt = 0; nt < 4; nt++) {
                int e  = en0 + nt * 8;
                int t0 = gg * 128 + 2 * e + thi;
                int t1 = gg * 128 + 2 * (e + 1) + thi;
                ob[(size_t)t0 * 1024 + d] = acc[mt][nt][hf * 2 + 0];
                ob[(size_t)t1 * 1024 + d] = acc[mt][nt][hf * 2 + 1];
            }
        }
    }
}

// ===========================================================================
// kernel_launch
// ===========================================================================
extern "C" void kernel_launch(void* const* d_in, const int* in_sizes, int n_in,
                              void* d_out, int out_size)
{
    const float* x  = (const float*)d_in[0];
    const float* sc = (const float*)d_in[1];
    const float* wq = (const float*)d_in[2];
    const float* bq = (const float*)d_in[3];
    const float* wk = (const float*)d_in[4];
    const float* bk = (const float*)d_in[5];
    const float* wv = (const float*)d_in[6];
    const float* bv = (const float*)d_in[7];

    float* out  = (float*)d_out;
    float* attn = out + OUT_ELEMS;

    float *q, *k, *v;
    __nv_bfloat16 *xh, *xl, *qh, *ql, *kh, *kl, *wh, *wl, *vh, *vl;
    cudaGetSymbolAddress((void**)&q,  g_q);
    cudaGetSymbolAddress((void**)&k,  g_k);
    cudaGetSymbolAddress((void**)&v,  g_v);
    cudaGetSymbolAddress((void**)&xh, g_xh);
    cudaGetSymbolAddress((void**)&xl, g_xl);
    cudaGetSymbolAddress((void**)&qh, g_qh);
    cudaGetSymbolAddress((void**)&ql, g_ql);
    cudaGetSymbolAddress((void**)&kh, g_kh);
    cudaGetSymbolAddress((void**)&kl, g_kl);
    cudaGetSymbolAddress((void**)&wh, g_wh);
    cudaGetSymbolAddress((void**)&wl, g_wl);
    cudaGetSymbolAddress((void**)&vh, g_vh);
    cudaGetSymbolAddress((void**)&vl, g_vl);

    cudaFuncSetAttribute(gemm_bb, cudaFuncAttributeMaxDynamicSharedMemorySize, GB_SMEM);
    cudaFuncSetAttribute(pv_fuse, cudaFuncAttributeMaxDynamicSharedMemorySize, PVF_SMEM);

    // 1) normalize x -> row-major hi/lo; split weights
    scalenorm_x<<<ROWS, 256>>>(x, sc, xh, xl);
    wsplit<<<3072, 256>>>(wq, wk, wv, wh, wl);

    // 2) projections (batched)
    gemm_bb<<<dim3(8, 32, 3), 256, GB_SMEM>>>(
        0, xh, xl, wh, wl, bq, bk, bv, q, k, v,
        DMODEL, DMODEL, DMODEL, DMODEL, 1.0f);

    // 3) scale_norm q/k/v
    scalenorm_qkv<<<dim3(ROWS, 3), 256>>>(q, k, v, sc, qh, ql, kh, kl);

    // 3b) V^T hi/lo split
    vt_convert<<<dim3(TSEQ / 64, 1, NGRP), 256>>>(v, vh, vl);

    // 4) S = Q K^T / 8 into attn region (raw logits)
    gemm_bb<<<dim3(16, 16, NGRP), 256, GB_SMEM>>>(
        1, qh, ql, kh, kl, nullptr, nullptr, nullptr, attn, nullptr, nullptr,
        DK, DK, TSEQ, DK, 0.125f);

    // 5+6) fused softmax + O = P @ V (writes normalized attn AND out)
    pv_fuse<<<dim3(TSEQ / 128, 1, NGRP), 256, PVF_SMEM>>>(attn, vh, vl, out);
}

// round 10
// speedup vs baseline: 1.1533x; 1.1043x over previous
#include <cuda_runtime.h>
#include <cuda_bf16.h>
#include <math.h>
#include <stdint.h>

#define ROWS   4096
#define DMODEL 1024
#define TSEQ   2048
#define DK     64
#define NGRP   32
#define OUT_ELEMS 4194304
#define ATTN_PER_G 4194304
#define GRP_STRIDE 131072

// Scratch
__device__ float g_q[ROWS * DMODEL];
__device__ float g_k[ROWS * DMODEL];
__device__ float g_v[ROWS * DMODEL];
__device__ __nv_bfloat16 g_xh[ROWS * DMODEL], g_xl[ROWS * DMODEL];
__device__ __nv_bfloat16 g_qh[ROWS * DMODEL], g_ql[ROWS * DMODEL];
__device__ __nv_bfloat16 g_kh[ROWS * DMODEL], g_kl[ROWS * DMODEL];
__device__ __nv_bfloat16 g_wh[3 * DMODEL * DMODEL], g_wl[3 * DMODEL * DMODEL];
__device__ __nv_bfloat16 g_vh[NGRP * DK * TSEQ], g_vl[NGRP * DK * TSEQ];
__device__ float2 g_pt[NGRP * 16 * TSEQ];   // softmax partials [g][colblk][row]

// ===========================================================================
__device__ __forceinline__ uint32_t smem_u32(const void* p) {
    uint32_t a;
    asm("{ .reg .u64 t; cvta.to.shared.u64 t, %1; cvt.u32.u64 %0, t; }"
        : "=r"(a) : "l"(p));
    return a;
}

__device__ __forceinline__ void ldsm4(uint32_t* r, uint32_t addr) {
    asm volatile("ldmatrix.sync.aligned.m8n8.x4.shared.b16 {%0,%1,%2,%3}, [%4];"
                 : "=r"(r[0]), "=r"(r[1]), "=r"(r[2]), "=r"(r[3]) : "r"(addr));
}

__device__ __forceinline__ void mma16816(float* c, const uint32_t* a,
                                         const uint32_t* b) {
    asm volatile(
        "mma.sync.aligned.m16n8k16.row.col.f32.bf16.bf16.f32 "
        "{%0,%1,%2,%3}, {%4,%5,%6,%7}, {%8,%9}, {%0,%1,%2,%3};"
        : "+f"(c[0]), "+f"(c[1]), "+f"(c[2]), "+f"(c[3])
        : "r"(a[0]), "r"(a[1]), "r"(a[2]), "r"(a[3]), "r"(b[0]), "r"(b[1]));
}

__device__ __forceinline__ void cpa16(uint32_t dst, const void* src) {
    asm volatile("cp.async.cg.shared.global [%0], [%1], 16;"
                 :: "r"(dst), "l"(src));
}
#define CP_COMMIT() asm volatile("cp.async.commit_group;" ::: "memory")
#define CP_WAIT(n)  asm volatile("cp.async.wait_group %0;" :: "n"(n) : "memory")

__device__ __forceinline__ void split_f4(float4 v, uint2& hi, uint2& lo) {
    uint32_t u0 = __float_as_uint(v.x), u1 = __float_as_uint(v.y);
    uint32_t u2 = __float_as_uint(v.z), u3 = __float_as_uint(v.w);
    hi.x = (u0 >> 16) | (u1 & 0xFFFF0000u);
    hi.y = (u2 >> 16) | (u3 & 0xFFFF0000u);
    float l0 = v.x - __uint_as_float(u0 & 0xFFFF0000u);
    float l1 = v.y - __uint_as_float(u1 & 0xFFFF0000u);
    float l2 = v.z - __uint_as_float(u2 & 0xFFFF0000u);
    float l3 = v.w - __uint_as_float(u3 & 0xFFFF0000u);
    __nv_bfloat162 p01 = __floats2bfloat162_rn(l0, l1);
    __nv_bfloat162 p23 = __floats2bfloat162_rn(l2, l3);
    lo.x = *reinterpret_cast<uint32_t*>(&p01);
    lo.y = *reinterpret_cast<uint32_t*>(&p23);
}

__device__ __forceinline__ float norm_factor(float ssq_part, float scale) {
    float ssq = ssq_part;
    #pragma unroll
    for (int o = 16; o > 0; o >>= 1) ssq += __shfl_xor_sync(0xffffffffu, ssq, o);
    __shared__ float ws[8];
    int w = threadIdx.x >> 5, l = threadIdx.x & 31;
    if (l == 0) ws[w] = ssq;
    __syncthreads();
    if (w == 0) {
        float s = (l < 8) ? ws[l] : 0.0f;
        #pragma unroll
        for (int o = 4; o > 0; o >>= 1) s += __shfl_xor_sync(0xffffffffu, s, o);
        if (l == 0) ws[0] = s;
    }
    __syncthreads();
    return scale / fmaxf(sqrtf(ws[0]), 1e-5f);
}

// ===========================================================================
// prep: blockIdx.x < 4096 -> scalenorm_x row; else -> wsplit block
// ===========================================================================
__global__ __launch_bounds__(256) void prep_kernel(
    const float* __restrict__ in, const float* __restrict__ scale_p,
    __nv_bfloat16* __restrict__ oh, __nv_bfloat16* __restrict__ ol,
    const float* __restrict__ w0, const float* __restrict__ w1,
    const float* __restrict__ w2,
    __nv_bfloat16* __restrict__ wh, __nv_bfloat16* __restrict__ wl)
{
    int t = threadIdx.x;
    if (blockIdx.x < 4096) {
        int r = blockIdx.x;
        float4 f = ((const float4*)in)[(size_t)r * 256 + t];
        float fac = norm_factor(f.x*f.x + f.y*f.y + f.z*f.z + f.w*f.w, scale_p[0]);
        f.x *= fac; f.y *= fac; f.z *= fac; f.w *= fac;
        uint2 hi, lo;
        split_f4(f, hi, lo);
        size_t off = (size_t)r * 1024 + t * 4;
        *(uint2*)((char*)oh + off * 2) = hi;
        *(uint2*)((char*)ol + off * 2) = lo;
    } else {
        size_t idx = ((size_t)(blockIdx.x - 4096) * 256 + t) * 4;
        int which = (int)(idx >> 20);
        const float* src = (which == 0) ? w0 : (which == 1) ? w1 : w2;
        float4 f = *(const float4*)(src + (idx & 1048575));
        uint2 hi, lo;
        split_f4(f, hi, lo);
        *(uint2*)((char*)wh + idx * 2) = hi;
        *(uint2*)((char*)wl + idx * 2) = lo;
    }
}

// ===========================================================================
// scalenorm_qkv: z=0 q->slab hi/lo, z=1 k->slab hi/lo, z=2 v in place
// ===========================================================================
__global__ __launch_bounds__(256) void scalenorm_qkv(
    const float* __restrict__ q, const float* __restrict__ k,
    float* __restrict__ v, const float* __restrict__ scale_p,
    __nv_bfloat16* __restrict__ qh, __nv_bfloat16* __restrict__ ql,
    __nv_bfloat16* __restrict__ kh, __nv_bfloat16* __restrict__ kl)
{
    int z = blockIdx.y, r = blockIdx.x, t = threadIdx.x;
    const float* in = (z == 0) ? q : (z == 1) ? k : v;
    float4 f = ((const float4*)in)[(size_t)r * 256 + t];
    float fac = norm_factor(f.x*f.x + f.y*f.y + f.z*f.z + f.w*f.w, scale_p[0]);
    f.x *= fac; f.y *= fac; f.z *= fac; f.w *= fac;

    if (z == 2) { ((float4*)v)[(size_t)r * 256 + t] = f; return; }
    uint2 hi, lo;
    split_f4(f, hi, lo);
    size_t off = (size_t)r * 1024 + t * 4;
    if (z == 1) {
        *(uint2*)((char*)kh + off * 2) = hi;
        *(uint2*)((char*)kl + off * 2) = lo;
    } else {
        *(uint2*)((char*)qh + off * 2) = hi;
        *(uint2*)((char*)ql + off * 2) = lo;
    }
}

// ===========================================================================
// V^T + hi/lo split
// ===========================================================================
__global__ __launch_bounds__(256) void vt_convert(
    const float* __restrict__ v,
    __nv_bfloat16* __restrict__ vh, __nv_bfloat16* __restrict__ vl)
{
    int g  = blockIdx.z;
    int k0 = blockIdx.x * 64;
    const float* vg = v + (size_t)g * GRP_STRIDE;
    __shared__ float sm[64][68];
    int t = threadIdx.x;
    int kr = t >> 2, f4 = (t & 3) * 4;
    const float4* rp = (const float4*)(vg + (size_t)(k0 + kr) * DK);
    #pragma unroll
    for (int i = 0; i < 4; i++) {
        float4 f = rp[f4 + i];
        *(float4*)&sm[kr][(f4 + i) * 4] = f;
    }
    __syncthreads();
    int n = t >> 2;
    size_t ob = (size_t)g * (DK * TSEQ) + (size_t)n * TSEQ + k0;
    #pragma unroll
    for (int j = 0; j < 4; j++) {
        int kk = (t & 3) * 16 + j * 4;
        float4 f = make_float4(sm[kk+0][n], sm[kk+1][n], sm[kk+2][n], sm[kk+3][n]);
        uint2 hi, lo;
        split_f4(f, hi, lo);
        *(uint2*)((char*)vh + (ob + kk) * 2) = hi;
        *(uint2*)((char*)vl + (ob + kk) * 2) = lo;
    }
}

// ===========================================================================
// gemm_bb: BM=128, BN=128, BK=32, cp.async 3-stage.
// mode 0: proj (z: wq/wk/wv).  mode 1: QK (z=group) + softmax partial stats.
// ===========================================================================
#define NSTAGE  3
#define STG_SZ  32768
#define GB_SMEM (NSTAGE * STG_SZ)

__global__ __launch_bounds__(256, 2) void gemm_bb(
    int mode,
    const __nv_bfloat16* __restrict__ Ah, const __nv_bfloat16* __restrict__ Al,
    const __nv_bfloat16* __restrict__ Bh, const __nv_bfloat16* __restrict__ Bl,
    const float* __restrict__ bias0, const float* __restrict__ bias1,
    const float* __restrict__ bias2,
    float* __restrict__ C0, float* __restrict__ C1, float* __restrict__ C2,
    int lda, int ldb, int ldc, int K, float alpha,
    float2* __restrict__ ps)
{
    extern __shared__ char smx[];
    uint32_t sbase = smem_u32(smx);

    const float* bias;
    float* C;
    int z = blockIdx.z;
    if (mode == 0) {
        Bh += (size_t)z * 1048576;  Bl += (size_t)z * 1048576;
        bias = (z == 0) ? bias0 : (z == 1) ? bias1 : bias2;
        C    = (z == 0) ? C0    : (z == 1) ? C1    : C2;
    } else {
        Ah += (size_t)z * 131072;   Al += (size_t)z * 131072;
        Bh += (size_t)z * 131072;   Bl += (size_t)z * 131072;
        bias = nullptr;
        C = C0 + (size_t)z * (size_t)ATTN_PER_G;
    }
    int rowBase = blockIdx.y * 128, colBase = blockIdx.x * 128;
    int tid = threadIdx.x, lane = tid & 31, wid = tid >> 5;
    int wm = wid >> 2, wn = wid & 3;

    int lr = tid >> 1, half = tid & 1;
    uint32_t swz = (lr >> 1) & 3;
    uint32_t d0 = lr * 64 + (((2u * half + 0) ^ swz) << 4);
    uint32_t d1 = lr * 64 + (((2u * half + 1) ^ swz) << 4);
    const char* aSrcH = (const char*)(Ah + (size_t)(rowBase + lr) * lda + half * 16);
    const char* aSrcL = (const char*)(Al + (size_t)(rowBase + lr) * lda + half * 16);
    const char* bSrcH = (const char*)(Bh + (size_t)(colBase + lr) * ldb + half * 16);
    const char* bSrcL = (const char*)(Bl + (size_t)(colBase + lr) * ldb + half * 16);

    int NC = K >> 5;

    auto issue = [&](int c, int s) {
        uint32_t st = sbase + s * STG_SZ;
        size_t ko = (size_t)c * 64;
        cpa16(st +         d0, aSrcH + ko);
        cpa16(st +         d1, aSrcH + ko + 16);
        cpa16(st +  8192 + d0, aSrcL + ko);
        cpa16(st +  8192 + d1, aSrcL + ko + 16);
        cpa16(st + 16384 + d0, bSrcH + ko);
        cpa16(st + 16384 + d1, bSrcH + ko + 16);
        cpa16(st + 24576 + d0, bSrcL + ko);
        cpa16(st + 24576 + d1, bSrcL + ko + 16);
        CP_COMMIT();
    };

    issue(0, 0);
    if (NC > 1) issue(1, 1);

    float acc[4][4][4];
    #pragma unroll
    for (int a = 0; a < 4; a++)
        #pragma unroll
        for (int b = 0; b < 4; b++)
            #pragma unroll
            for (int r = 0; r < 4; r++) acc[a][b][r] = 0.0f;

    int stage = 0;
    for (int c = 0; c < NC; c++) {
        if (c < NC - 1) CP_WAIT(1); else CP_WAIT(0);
        __syncthreads();
        if (c + NSTAGE - 1 < NC)
            issue(c + NSTAGE - 1, (stage + NSTAGE - 1) % NSTAGE);

        uint32_t stA = sbase + stage * STG_SZ;
        uint32_t stB = stA + 16384;
        #pragma unroll
        for (int kk = 0; kk < 2; kk++) {
            uint32_t ah[4][4], al[4][4];
            #pragma unroll
            for (int mt = 0; mt < 4; mt++) {
                int r = wm * 64 + mt * 16 + (lane & 15);
                uint32_t c16 = kk * 2 + (lane >> 4);
                uint32_t off = r * 64 + ((c16 ^ ((r >> 1) & 3)) << 4);
                ldsm4(ah[mt], stA + off);
                ldsm4(al[mt], stA + 8192 + off);
            }
            uint32_t bh[2][4], bl[2][4];
            #pragma unroll
            for (int np = 0; np < 2; np++) {
                int r = wn * 32 + np * 16 + ((lane >> 4) << 3) + (lane & 7);
                uint32_t c16 = kk * 2 + ((lane >> 3) & 1);
                uint32_t off = r * 64 + ((c16 ^ ((r >> 1) & 3)) << 4);
                ldsm4(bh[np], stB + off);
                ldsm4(bl[np], stB + 8192 + off);
            }
            #pragma unroll
            for (int mt = 0; mt < 4; mt++)
                #pragma unroll
                for (int nt = 0; nt < 4; nt++) {
                    const uint32_t* ph = &bh[nt >> 1][(nt & 1) * 2];
                    const uint32_t* pl = &bl[nt >> 1][(nt & 1) * 2];
                    mma16816(acc[mt][nt], ah[mt], ph);
                    mma16816(acc[mt][nt], ah[mt], pl);
                    mma16816(acc[mt][nt], al[mt], ph);
                }
        }
        __syncthreads();
        stage = (stage + 1) % NSTAGE;
    }

    int r0 = rowBase + wm * 64 + (lane >> 2);
    int c0 = colBase + wn * 32 + (lane & 3) * 2;
    #pragma unroll
    for (int nt = 0; nt < 4; nt++) {
        int col = c0 + nt * 8;
        float b0 = 0.0f, b1 = 0.0f;
        if (bias) { b0 = bias[col]; b1 = bias[col + 1]; }
        #pragma unroll
        for (int mt = 0; mt < 4; mt++) {
            int row = r0 + mt * 16;
            *(float2*)(C + (size_t)row * ldc + col) =
                make_float2(acc[mt][nt][0] * alpha + b0,
                            acc[mt][nt][1] * alpha + b1);
            *(float2*)(C + (size_t)(row + 8) * ldc + col) =
                make_float2(acc[mt][nt][2] * alpha + b0,
                            acc[mt][nt][3] * alpha + b1);
        }
    }

    // softmax partial stats for this 128x128 tile (mode 1 only)
    if (ps) {
        float* pm = (float*)smx;             // [4 wn][128 rows]
        float* pu = (float*)(smx + 2048);    // [4 wn][128 rows]
        #pragma unroll
        for (int mt = 0; mt < 4; mt++)
            #pragma unroll
            for (int hf = 0; hf < 2; hf++) {
                float m = -3.4e38f;
                #pragma unroll
                for (int nt = 0; nt < 4; nt++)
                    m = fmaxf(m, fmaxf(acc[mt][nt][hf*2] * alpha,
                                       acc[mt][nt][hf*2+1] * alpha));
                m = fmaxf(m, __shfl_xor_sync(0xffffffffu, m, 1));
                m = fmaxf(m, __shfl_xor_sync(0xffffffffu, m, 2));
                float s = 0.0f;
                #pragma unroll
                for (int nt = 0; nt < 4; nt++)
                    s += __expf(acc[mt][nt][hf*2] * alpha - m)
                       + __expf(acc[mt][nt][hf*2+1] * alpha - m);
                s += __shfl_xor_sync(0xffffffffu, s, 1);
                s += __shfl_xor_sync(0xffffffffu, s, 2);
                if ((lane & 3) == 0) {
                    int lrow = wm * 64 + mt * 16 + hf * 8 + (lane >> 2);
                    pm[wn * 128 + lrow] = m;
                    pu[wn * 128 + lrow] = s;
                }
            }
        __syncthreads();
        if (tid < 128) {
            float m = -3.4e38f;
            #pragma unroll
            for (int i = 0; i < 4; i++) m = fmaxf(m, pm[i * 128 + tid]);
            float s = 0.0f;
            #pragma unroll
            for (int i = 0; i < 4; i++)
                s += pu[i * 128 + tid] * __expf(pm[i * 128 + tid] - m);
            ps[((size_t)z * 16 + blockIdx.x) * TSEQ + rowBase + tid] =
                make_float2(m, s);
        }
    }
}

// ===========================================================================
// pv_fuse: stats from partials; per 32-col chunk: p = exp(v-m)*inv;
// write normalized attn; split->smem; MMA with V^T tiles; scatter epilogue.
// ===========================================================================
#define PVF_S_OFF   0
#define PVF_V_OFF   49152
#define PVF_A_OFF   73728
#define PVF_M_OFF   106496
#define PVF_SMEM    107520

__global__ __launch_bounds__(256, 2) void pv_fuse(
    float* __restrict__ attn, const float2* __restrict__ pt,
    const __nv_bfloat16* __restrict__ Vh, const __nv_bfloat16* __restrict__ Vl,
    float* __restrict__ Out)
{
    extern __shared__ char smx[];
    uint32_t sbase = smem_u32(smx);
    float* sm_m   = (float*)(smx + PVF_M_OFF);
    float* sm_inv = (float*)(smx + PVF_M_OFF + 512);

    int g = blockIdx.z;
    int rowBase = blockIdx.x * 128;
    float* Sg = attn + (size_t)g * ATTN_PER_G;
    const __nv_bfloat16* VhG = Vh + (size_t)g * (DK * TSEQ);
    const __nv_bfloat16* VlG = Vl + (size_t)g * (DK * TSEQ);

    int tid = threadIdx.x, lane = tid & 31, wid = tid >> 5;
    int wm = wid >> 1, wn = wid & 1;

    int br = tid >> 1, bhf = tid & 1;
    uint32_t bswz = (br >> 1) & 3;
    uint32_t e0 = br * 64 + (((2u * bhf + 0) ^ bswz) << 4);
    uint32_t e1 = br * 64 + (((2u * bhf + 1) ^ bswz) << 4);
    const char* bSrcH = (const char*)(VhG + (size_t)br * TSEQ + bhf * 16);
    const char* bSrcL = (const char*)(VlG + (size_t)br * TSEQ + bhf * 16);

    auto issue = [&](int c, int s) {
        uint32_t stS = sbase + PVF_S_OFF + s * 16384;
        #pragma unroll
        for (int t4 = 0; t4 < 4; t4++) {
            int id = tid + t4 * 256;
            int r = id >> 3, c16 = id & 7;
            cpa16(stS + r * 128 + c16 * 16,
                  (const char*)(Sg + (size_t)(rowBase + r) * TSEQ) + c * 128 + c16 * 16);
        }
        if (tid < 128) {
            uint32_t stV = sbase + PVF_V_OFF + s * 8192;
            size_t ko = (size_t)c * 64;
            cpa16(stV +        e0, bSrcH + ko);
            cpa16(stV +        e1, bSrcH + ko + 16);
            cpa16(stV + 4096 + e0, bSrcL + ko);
            cpa16(stV + 4096 + e1, bSrcL + ko + 16);
        }
        CP_COMMIT();
    };

    issue(0, 0);
    issue(1, 1);

    // stats from partials (16 colblocks)
    if (tid < 128) {
        const float2* pp = pt + (size_t)g * 16 * TSEQ + rowBase + tid;
        float m = -3.4e38f, s = 0.0f;
        #pragma unroll
        for (int i = 0; i < 16; i++) {
            float2 q = pp[(size_t)i * TSEQ];
            float mn = fmaxf(m, q.x);
            s = s * __expf(m - mn) + q.y * __expf(q.x - mn);
            m = mn;
        }
        sm_m[tid] = m;
        sm_inv[tid] = 1.0f / s;
    }
    __syncthreads();

    float acc[2][4][4];
    #pragma unroll
    for (int a = 0; a < 2; a++)
        #pragma unroll
        for (int b = 0; b < 4; b++)
            #pragma unroll
            for (int r = 0; r < 4; r++) acc[a][b][r] = 0.0f;

    const int NC = TSEQ >> 5;   // 64
    int stage = 0;
    for (int c = 0; c < NC; c++) {
        if (c < NC - 1) CP_WAIT(1); else CP_WAIT(0);
        __syncthreads();
        if (c + 2 < NC) issue(c + 2, (stage + 2) % NSTAGE);

        char* conv = smx + PVF_A_OFF + (c & 1) * 16384;

        #pragma unroll
        for (int it = 0; it < 4; it++) {
            int r  = (tid >> 3) + it * 32;
            int c4 = tid & 7;
            float4 f = *(float4*)(smx + PVF_S_OFF + stage * 16384 + r * 128 + c4 * 16);
            float mm = sm_m[r], iv = sm_inv[r];
            float4 p;
            p.x = __expf(f.x - mm) * iv;
            p.y = __expf(f.y - mm) * iv;
            p.z = __expf(f.z - mm) * iv;
            p.w = __expf(f.w - mm) * iv;
            *(float4*)(Sg + (size_t)(rowBase + r) * TSEQ + c * 32 + c4 * 4) = p;
            uint2 h, l;
            split_f4(p, h, l);
            uint32_t c16h = (uint32_t)(c4 >> 1);
            uint32_t sub  = (c4 & 1) * 8;
            uint32_t aoff = r * 64 + ((c16h ^ ((r >> 1) & 3)) << 4) + sub;
            *(uint2*)(conv +        aoff) = h;
            *(uint2*)(conv + 8192 + aoff) = l;
        }
        __syncthreads();

        uint32_t stA = sbase + PVF_A_OFF + (c & 1) * 16384;
        uint32_t stB = sbase + PVF_V_OFF + stage * 8192;
        #pragma unroll
        for (int kk = 0; kk < 2; kk++) {
            uint32_t ah[2][4], al[2][4];
            #pragma unroll
            for (int mt = 0; mt < 2; mt++) {
                int r = wm * 32 + mt * 16 + (lane & 15);
                uint32_t c16 = kk * 2 + (lane >> 4);
                uint32_t off = r * 64 + ((c16 ^ ((r >> 1) & 3)) << 4);
                ldsm4(ah[mt], stA + off);
                ldsm4(al[mt], stA + 8192 + off);
            }
            uint32_t bh[2][4], bl[2][4];
            #pragma unroll
            for (int np = 0; np < 2; np++) {
                int r = wn * 32 + np * 16 + ((lane >> 4) << 3) + (lane & 7);
                uint32_t c16 = kk * 2 + ((lane >> 3) & 1);
                uint32_t off = r * 64 + ((c16 ^ ((r >> 1) & 3)) << 4);
                ldsm4(bh[np], stB + off);
                ldsm4(bl[np], stB + 4096 + off);
            }
            #pragma unroll
            for (int mt = 0; mt < 2; mt++)
                #pragma unroll
                for (int nt = 0; nt < 4; nt++) {
                    const uint32_t* ph = &bh[nt >> 1][(nt & 1) * 2];
                    const uint32_t* pl = &bl[nt >> 1][(nt & 1) * 2];
                    mma16816(acc[mt][nt], ah[mt], ph);
                    mma16816(acc[mt][nt], ah[mt], pl);
                    mma16816(acc[mt][nt], al[mt], ph);
                }
        }
        stage = (stage + 1) % NSTAGE;
    }

    // scatter epilogue (validated)
    int b  = g >> 4;
    int gg = g & 15;
    float* ob = Out + (size_t)b * 2097152;
    int rr  = rowBase + wm * 32 + (lane >> 2);
    int en0 = wn * 32 + (lane & 3) * 2;
    #pragma unroll
    for (int mt = 0; mt < 2; mt++) {
        #pragma unroll
        for (int hf = 0; hf < 2; hf++) {
            int s   = rr + mt * 16 + hf * 8;
            int thi = s >> 10;
            int d   = s & 1023;
            #pragma unroll
            for (int nt = 0; nt < 4; nt++) {
                int e  = en0 + nt * 8;
                int t0 = gg * 128 + 2 * e + thi;
                int t1 = gg * 128 + 2 * (e + 1) + thi;
                ob[(size_t)t0 * 1024 + d] = acc[mt][nt][hf * 2 + 0];
                ob[(size_t)t1 * 1024 + d] = acc[mt][nt][hf * 2 + 1];
            }
        }
    }
}

// ===========================================================================
// kernel_launch
// ===========================================================================
extern "C" void kernel_launch(void* const* d_in, const int* in_sizes, int n_in,
                              void* d_out, int out_size)
{
    const float* x  = (const float*)d_in[0];
    const float* sc = (const float*)d_in[1];
    const float* wq = (const float*)d_in[2];
    const float* bq = (const float*)d_in[3];
    const float* wk = (const float*)d_in[4];
    const float* bk = (const float*)d_in[5];
    const float* wv = (const float*)d_in[6];
    const float* bv = (const float*)d_in[7];

    float* out  = (float*)d_out;
    float* attn = out + OUT_ELEMS;

    float *q, *k, *v;
    float2* pt;
    __nv_bfloat16 *xh, *xl, *qh, *ql, *kh, *kl, *wh, *wl, *vh, *vl;
    cudaGetSymbolAddress((void**)&q,  g_q);
    cudaGetSymbolAddress((void**)&k,  g_k);
    cudaGetSymbolAddress((void**)&v,  g_v);
    cudaGetSymbolAddress((void**)&xh, g_xh);
    cudaGetSymbolAddress((void**)&xl, g_xl);
    cudaGetSymbolAddress((void**)&qh, g_qh);
    cudaGetSymbolAddress((void**)&ql, g_ql);
    cudaGetSymbolAddress((void**)&kh, g_kh);
    cudaGetSymbolAddress((void**)&kl, g_kl);
    cudaGetSymbolAddress((void**)&wh, g_wh);
    cudaGetSymbolAddress((void**)&wl, g_wl);
    cudaGetSymbolAddress((void**)&vh, g_vh);
    cudaGetSymbolAddress((void**)&vl, g_vl);
    cudaGetSymbolAddress((void**)&pt, g_pt);

    cudaFuncSetAttribute(gemm_bb, cudaFuncAttributeMaxDynamicSharedMemorySize, GB_SMEM);
    cudaFuncSetAttribute(pv_fuse, cudaFuncAttributeMaxDynamicSharedMemorySize, PVF_SMEM);

    // 1) normalize x + split weights (fused launch)
    prep_kernel<<<4096 + 3072, 256>>>(x, sc, xh, xl, wq, wk, wv, wh, wl);

    // 2) projections (batched)
    gemm_bb<<<dim3(8, 32, 3), 256, GB_SMEM>>>(
        0, xh, xl, wh, wl, bq, bk, bv, q, k, v,
        DMODEL, DMODEL, DMODEL, DMODEL, 1.0f, nullptr);

    // 3) scale_norm q/k/v
    scalenorm_qkv<<<dim3(ROWS, 3), 256>>>(q, k, v, sc, qh, ql, kh, kl);

    // 3b) V^T hi/lo split
    vt_convert<<<dim3(TSEQ / 64, 1, NGRP), 256>>>(v, vh, vl);

    // 4) S = Q K^T / 8 into attn region + per-tile softmax partials
    gemm_bb<<<dim3(16, 16, NGRP), 256, GB_SMEM>>>(
        1, qh, ql, kh, kl, nullptr, nullptr, nullptr, attn, nullptr, nullptr,
        DK, DK, TSEQ, DK, 0.125f, pt);

    // 5+6) fused softmax + O = P @ V (writes normalized attn AND out)
    pv_fuse<<<dim3(TSEQ / 128, 1, NGRP), 256, PVF_SMEM>>>(attn, pt, vh, vl, out);
}